// round 7
// baseline (speedup 1.0000x reference)
#include <cuda_runtime.h>

#define VD 160
#define VH 192
#define VW 160
#define NB 2
#define NVOX (VD * VH * VW)          // 4,915,200 voxels per batch
#define NTOT (NB * NVOX)             // 9,830,400

// Ping-pong scratch, AoS-float4 layout (157 MB each).
__device__ float4 g_a[(size_t)NTOT];
__device__ float4 g_b[(size_t)NTOT];

// AoS float3 input -> AoS float4 scratch, fused initial scale (vel / 2^7).
__global__ void __launch_bounds__(256)
pack4_scale(const float* __restrict__ in, float4* __restrict__ out, float scale)
{
    unsigned v = blockIdx.x * 256u + threadIdx.x;
    if (v >= (unsigned)NTOT) return;
    size_t base = (size_t)v * 3u;
    float a = in[base], b = in[base + 1], c = in[base + 2];
    out[v] = make_float4(a * scale, b * scale, c * scale, 0.0f);
}

// One scaling-and-squaring step on float4-AoS data.
// AOS_OUT=1: write packed float3 AoS into d_out (final step).
template <int AOS_OUT>
__global__ void __launch_bounds__(256)
vstep4(const float4* __restrict__ src, float4* __restrict__ dstV,
       float* __restrict__ dstA)
{
    unsigned idx = blockIdx.x * 256u + threadIdx.x;
    if (idx >= (unsigned)NTOT) return;

    unsigned b = idx / (unsigned)NVOX;
    unsigned v = idx - b * (unsigned)NVOX;

    unsigned z = v % VW;
    unsigned t = v / VW;
    unsigned y = t % VH;
    unsigned x = t / VH;

    const float4* __restrict__ vol = src + (size_t)b * NVOX;

    // Center displacement (one LDG.128)
    float4 ctr = vol[v];
    float dx = ctr.x, dy = ctr.y, dz = ctr.z;

    // Sample location = identity + disp, clamped (matches reference clip)
    float lx = fminf(fmaxf((float)x + dx, 0.0f), (float)(VD - 1));
    float ly = fminf(fmaxf((float)y + dy, 0.0f), (float)(VH - 1));
    float lz = fminf(fmaxf((float)z + dz, 0.0f), (float)(VW - 1));

    float fx = floorf(lx), fy = floorf(ly), fz = floorf(lz);
    float wx = lx - fx,  wy = ly - fy,  wz = lz - fz;

    int x0 = (int)fx, y0 = (int)fy, z0 = (int)fz;
    int x1 = min(x0 + 1, VD - 1);
    int y1 = min(y0 + 1, VH - 1);
    int z1 = min(z0 + 1, VW - 1);

    unsigned rb00 = ((unsigned)x0 * VH + (unsigned)y0) * VW;
    unsigned rb01 = ((unsigned)x0 * VH + (unsigned)y1) * VW;
    unsigned rb10 = ((unsigned)x1 * VH + (unsigned)y0) * VW;
    unsigned rb11 = ((unsigned)x1 * VH + (unsigned)y1) * VW;

    // Multilinear weights (algebraically identical to nested lerp)
    float owz = 1.0f - wz, owy = 1.0f - wy, owx = 1.0f - wx;
    float w00 = owx * owy, w01 = owx * wy, w10 = wx * owy, w11 = wx * wy;
    float w000 = w00 * owz, w001 = w00 * wz;
    float w010 = w01 * owz, w011 = w01 * wz;
    float w100 = w10 * owz, w101 = w10 * wz;
    float w110 = w11 * owz, w111 = w11 * wz;

    // 8 corner fetches, one LDG.128 each (all 3 channels at once)
    float4 g000 = vol[rb00 + (unsigned)z0];
    float4 g001 = vol[rb00 + (unsigned)z1];
    float4 g010 = vol[rb01 + (unsigned)z0];
    float4 g011 = vol[rb01 + (unsigned)z1];
    float4 g100 = vol[rb10 + (unsigned)z0];
    float4 g101 = vol[rb10 + (unsigned)z1];
    float4 g110 = vol[rb11 + (unsigned)z0];
    float4 g111 = vol[rb11 + (unsigned)z1];

    float sx = g000.x * w000 + g001.x * w001 + g010.x * w010 + g011.x * w011
             + g100.x * w100 + g101.x * w101 + g110.x * w110 + g111.x * w111;
    float sy = g000.y * w000 + g001.y * w001 + g010.y * w010 + g011.y * w011
             + g100.y * w100 + g101.y * w101 + g110.y * w110 + g111.y * w111;
    float sz = g000.z * w000 + g001.z * w001 + g010.z * w010 + g011.z * w011
             + g100.z * w100 + g101.z * w101 + g110.z * w110 + g111.z * w111;

    if (AOS_OUT) {
        float* __restrict__ out = dstA + (size_t)idx * 3u;
        out[0] = dx + sx;
        out[1] = dy + sy;
        out[2] = dz + sz;
    } else {
        dstV[idx] = make_float4(dx + sx, dy + sy, dz + sz, 0.0f);
    }
}

extern "C" void kernel_launch(void* const* d_in, const int* in_sizes, int n_in,
                              void* d_out, int out_size)
{
    const float* vel = (const float*)d_in[0];
    float* out = (float*)d_out;
    float4 *a = nullptr, *bb = nullptr;
    cudaGetSymbolAddress((void**)&a, g_a);
    cudaGetSymbolAddress((void**)&bb, g_b);

    const int threads = 256;
    const int blocksV = (NTOT + threads - 1) / threads;
    const float s0 = 1.0f / 128.0f;   // OUT_TIME_PT / 2^INT_STEPS

    // v0 = vel / 128, packed to float4 AoS
    pack4_scale<<<blocksV, threads>>>(vel, a, s0);
    // 7 squaring steps; last one writes float3 AoS directly into d_out
    vstep4<0><<<blocksV, threads>>>(a, bb, nullptr);
    vstep4<0><<<blocksV, threads>>>(bb, a, nullptr);
    vstep4<0><<<blocksV, threads>>>(a, bb, nullptr);
    vstep4<0><<<blocksV, threads>>>(bb, a, nullptr);
    vstep4<0><<<blocksV, threads>>>(a, bb, nullptr);
    vstep4<0><<<blocksV, threads>>>(bb, a, nullptr);
    vstep4<1><<<blocksV, threads>>>(a, nullptr, out);
}

// round 10
// speedup vs baseline: 1.0229x; 1.0229x over previous
#include <cuda_runtime.h>
#include <cuda_fp16.h>

#define VD 160
#define VH 192
#define VW 160
#define NB 2
#define NVOX (VD * VH * VW)          // 4,915,200 voxels per batch
#define NTOT (NB * NVOX)             // 9,830,400

// fp32 SoA ping-pong (primary, exact) + fp16 SoA mirrors (gather source).
__device__ float  g_f32a[(size_t)NTOT * 3];
__device__ float  g_f32b[(size_t)NTOT * 3];
__device__ __half g_h16a[(size_t)NTOT * 3];
__device__ __half g_h16b[(size_t)NTOT * 3];

// AoS float3 -> SoA fp32 + fp16 mirror, fused initial scale (vel / 2^7).
__global__ void __launch_bounds__(256)
transpose_scale(const float* __restrict__ in, float* __restrict__ outF,
                __half* __restrict__ outH, float scale)
{
    unsigned i = blockIdx.x * 256u + threadIdx.x;
    if (i >= (unsigned)(NTOT * 3)) return;
    unsigned b = i / (unsigned)(NVOX * 3);
    unsigned e = i - b * (unsigned)(NVOX * 3);
    unsigned v = e / 3u;
    unsigned c = e - v * 3u;
    float val = in[i] * scale;
    size_t o = (size_t)b * NVOX * 3 + (size_t)c * NVOX + v;
    outF[o] = val;
    outH[o] = __float2half_rn(val);
}

// One scaling-and-squaring step. Centers/accumulation fp32; corner gathers fp16.
// AOS_OUT=1: final step, write packed float3 AoS into d_out (no mirror write).
template <int AOS_OUT>
__global__ void __launch_bounds__(256)
vstep_h(const float* __restrict__ srcF, const __half* __restrict__ srcH,
        float* __restrict__ dstF, __half* __restrict__ dstH,
        float* __restrict__ dstA)
{
    unsigned idx = blockIdx.x * 256u + threadIdx.x;
    if (idx >= (unsigned)NTOT) return;

    unsigned b = idx / (unsigned)NVOX;
    unsigned v = idx - b * (unsigned)NVOX;

    unsigned z = v % VW;
    unsigned t = v / VW;
    unsigned y = t % VH;
    unsigned x = t / VH;

    const float*  __restrict__ pF = srcF + (size_t)b * NVOX * 3;
    const __half* __restrict__ h0 = srcH + (size_t)b * NVOX * 3;
    const __half* __restrict__ h1 = h0 + NVOX;
    const __half* __restrict__ h2 = h0 + 2 * NVOX;

    // Exact fp32 center displacement
    float dx = pF[v];
    float dy = pF[v + NVOX];
    float dz = pF[v + 2 * NVOX];

    // Sample location = identity + disp, clamped (matches reference clip)
    float lx = fminf(fmaxf((float)x + dx, 0.0f), (float)(VD - 1));
    float ly = fminf(fmaxf((float)y + dy, 0.0f), (float)(VH - 1));
    float lz = fminf(fmaxf((float)z + dz, 0.0f), (float)(VW - 1));

    float fx = floorf(lx), fy = floorf(ly), fz = floorf(lz);
    float wx = lx - fx,  wy = ly - fy,  wz = lz - fz;

    int x0 = (int)fx, y0 = (int)fy, z0 = (int)fz;
    int x1 = min(x0 + 1, VD - 1);
    int y1 = min(y0 + 1, VH - 1);
    int z1 = min(z0 + 1, VW - 1);

    unsigned rb00 = ((unsigned)x0 * VH + (unsigned)y0) * VW;
    unsigned rb01 = ((unsigned)x0 * VH + (unsigned)y1) * VW;
    unsigned rb10 = ((unsigned)x1 * VH + (unsigned)y0) * VW;
    unsigned rb11 = ((unsigned)x1 * VH + (unsigned)y1) * VW;

    unsigned o000 = rb00 + (unsigned)z0, o001 = rb00 + (unsigned)z1;
    unsigned o010 = rb01 + (unsigned)z0, o011 = rb01 + (unsigned)z1;
    unsigned o100 = rb10 + (unsigned)z0, o101 = rb10 + (unsigned)z1;
    unsigned o110 = rb11 + (unsigned)z0, o111 = rb11 + (unsigned)z1;

    float owz = 1.0f - wz, owy = 1.0f - wy, owx = 1.0f - wx;

    float s[3];
    const __half* planes[3] = {h0, h1, h2};
#pragma unroll
    for (int c = 0; c < 3; c++) {
        const __half* __restrict__ pl = planes[c];
        float g000 = __half2float(pl[o000]), g001 = __half2float(pl[o001]);
        float g010 = __half2float(pl[o010]), g011 = __half2float(pl[o011]);
        float g100 = __half2float(pl[o100]), g101 = __half2float(pl[o101]);
        float g110 = __half2float(pl[o110]), g111 = __half2float(pl[o111]);

        float c00 = g000 * owz + g001 * wz;
        float c01 = g010 * owz + g011 * wz;
        float c10 = g100 * owz + g101 * wz;
        float c11 = g110 * owz + g111 * wz;

        float c0 = c00 * owy + c01 * wy;
        float c1 = c10 * owy + c11 * wy;
        s[c] = c0 * owx + c1 * wx;
    }

    float rx = dx + s[0];
    float ry = dy + s[1];
    float rz = dz + s[2];

    if (AOS_OUT) {
        float* __restrict__ out = dstA + (size_t)idx * 3u;
        out[0] = rx;
        out[1] = ry;
        out[2] = rz;
    } else {
        float*  __restrict__ oF = dstF + (size_t)b * NVOX * 3;
        __half* __restrict__ oH = dstH + (size_t)b * NVOX * 3;
        oF[v]            = rx;
        oF[v + NVOX]     = ry;
        oF[v + 2 * NVOX] = rz;
        oH[v]            = __float2half_rn(rx);
        oH[v + NVOX]     = __float2half_rn(ry);
        oH[v + 2 * NVOX] = __float2half_rn(rz);
    }
}

extern "C" void kernel_launch(void* const* d_in, const int* in_sizes, int n_in,
                              void* d_out, int out_size)
{
    const float* vel = (const float*)d_in[0];
    float* out = (float*)d_out;
    float *fa = nullptr, *fb = nullptr;
    __half *ha = nullptr, *hb = nullptr;
    cudaGetSymbolAddress((void**)&fa, g_f32a);
    cudaGetSymbolAddress((void**)&fb, g_f32b);
    cudaGetSymbolAddress((void**)&ha, g_h16a);
    cudaGetSymbolAddress((void**)&hb, g_h16b);

    const int threads = 256;
    const int blocksV = (NTOT + threads - 1) / threads;
    const int blocksE = (NTOT * 3 + threads - 1) / threads;
    const float s0 = 1.0f / 128.0f;   // OUT_TIME_PT / 2^INT_STEPS

    // v0 = vel / 128, SoA fp32 + fp16 mirror
    transpose_scale<<<blocksE, threads>>>(vel, fa, ha, s0);
    // 7 squaring steps; last writes float3 AoS directly into d_out
    vstep_h<0><<<blocksV, threads>>>(fa, ha, fb, hb, nullptr);
    vstep_h<0><<<blocksV, threads>>>(fb, hb, fa, ha, nullptr);
    vstep_h<0><<<blocksV, threads>>>(fa, ha, fb, hb, nullptr);
    vstep_h<0><<<blocksV, threads>>>(fb, hb, fa, ha, nullptr);
    vstep_h<0><<<blocksV, threads>>>(fa, ha, fb, hb, nullptr);
    vstep_h<0><<<blocksV, threads>>>(fb, hb, fa, ha, nullptr);
    vstep_h<1><<<blocksV, threads>>>(fa, ha, nullptr, nullptr, out);
}

// round 11
// speedup vs baseline: 1.2177x; 1.1904x over previous
#include <cuda_runtime.h>
#include <cuda_fp16.h>

#define VD 160
#define VH 192
#define VW 160
#define NB 2
#define NVOX (VD * VH * VW)          // 4,915,200 voxels per batch
#define NTOT (NB * NVOX)             // 9,830,400

// fp32 SoA ping-pong (exact centers) + fp16 z-pair gather arrays.
// Pxy[p] = half2(x[p],y[p]) , half2(x[p+1],y[p+1])   (uint2, 8B)
// Pz [p] = half2(z[p], z[p+1])                        (uint, 4B)
__device__ float g_f32a[(size_t)NTOT * 3];
__device__ float g_f32b[(size_t)NTOT * 3];
__device__ uint2 g_pxa[(size_t)NTOT];
__device__ uint2 g_pxb[(size_t)NTOT];
__device__ unsigned g_pza[(size_t)NTOT];
__device__ unsigned g_pzb[(size_t)NTOT];

__device__ __forceinline__ unsigned h2u(__half2 h) {
    return *reinterpret_cast<unsigned*>(&h);
}

// Write one voxel's result into fp32 SoA + pair arrays (self .lo, predecessor .hi)
__device__ __forceinline__ void store_all(
    unsigned idx, unsigned b, unsigned v,
    float rx, float ry, float rz,
    float* __restrict__ dstF, uint2* __restrict__ dstXY, unsigned* __restrict__ dstZ)
{
    float* oF = dstF + (size_t)b * NVOX * 3;
    oF[v]            = rx;
    oF[v + NVOX]     = ry;
    oF[v + 2 * NVOX] = rz;

    unsigned hxy = h2u(__floats2half2_rn(rx, ry));
    __half hz = __float2half_rn(rz);

    unsigned* pxw = reinterpret_cast<unsigned*>(dstXY);
    __half*   pzw = reinterpret_cast<__half*>(dstZ);
    pxw[2u * idx] = hxy;              // Pxy[idx].lo
    pzw[2u * idx] = hz;               // Pz[idx].x
    if (idx > 0) {
        pxw[2u * idx - 1u] = hxy;     // Pxy[idx-1].hi
        pzw[2u * idx - 1u] = hz;      // Pz[idx-1].y
    }
}

// AoS float3 input -> fp32 SoA + pair arrays, fused initial scale (vel / 2^7).
__global__ void __launch_bounds__(256)
init_fields(const float* __restrict__ in, float* __restrict__ dstF,
            uint2* __restrict__ dstXY, unsigned* __restrict__ dstZ, float scale)
{
    unsigned idx = blockIdx.x * 256u + threadIdx.x;
    if (idx >= (unsigned)NTOT) return;
    unsigned b = idx / (unsigned)NVOX;
    unsigned v = idx - b * (unsigned)NVOX;
    size_t base = (size_t)idx * 3u;
    float rx = in[base] * scale;
    float ry = in[base + 1] * scale;
    float rz = in[base + 2] * scale;
    store_all(idx, b, v, rx, ry, rz, dstF, dstXY, dstZ);
}

// One scaling-and-squaring step. Centers fp32; gathers via fp16 pair arrays.
// AOS_OUT=1: final step, write packed float3 AoS into d_out.
template <int AOS_OUT>
__global__ void __launch_bounds__(256)
vstep_p(const float* __restrict__ srcF, const uint2* __restrict__ srcXY,
        const unsigned* __restrict__ srcZ,
        float* __restrict__ dstF, uint2* __restrict__ dstXY,
        unsigned* __restrict__ dstZ, float* __restrict__ dstA)
{
    unsigned idx = blockIdx.x * 256u + threadIdx.x;
    if (idx >= (unsigned)NTOT) return;

    unsigned b = idx / (unsigned)NVOX;
    unsigned v = idx - b * (unsigned)NVOX;

    unsigned z = v % VW;
    unsigned t = v / VW;
    unsigned y = t % VH;
    unsigned x = t / VH;

    const float* __restrict__ pF = srcF + (size_t)b * NVOX * 3;
    const uint2* __restrict__ pXY = srcXY + (size_t)b * NVOX;
    const unsigned* __restrict__ pZ = srcZ + (size_t)b * NVOX;

    // Exact fp32 center displacement
    float dx = pF[v];
    float dy = pF[v + NVOX];
    float dz = pF[v + 2 * NVOX];

    // Sample location = identity + disp, clamped (matches reference clip)
    float lx = fminf(fmaxf((float)x + dx, 0.0f), (float)(VD - 1));
    float ly = fminf(fmaxf((float)y + dy, 0.0f), (float)(VH - 1));
    float lz = fminf(fmaxf((float)z + dz, 0.0f), (float)(VW - 1));

    float fx = floorf(lx), fy = floorf(ly), fz = floorf(lz);
    float wx = lx - fx,  wy = ly - fy,  wz = lz - fz;

    int x0 = (int)fx, y0 = (int)fy, z0 = (int)fz;
    int x1 = min(x0 + 1, VD - 1);
    int y1 = min(y0 + 1, VH - 1);

    unsigned o00 = ((unsigned)x0 * VH + (unsigned)y0) * VW + (unsigned)z0;
    unsigned o01 = ((unsigned)x0 * VH + (unsigned)y1) * VW + (unsigned)z0;
    unsigned o10 = ((unsigned)x1 * VH + (unsigned)y0) * VW + (unsigned)z0;
    unsigned o11 = ((unsigned)x1 * VH + (unsigned)y1) * VW + (unsigned)z0;

    float owz = 1.0f - wz, owy = 1.0f - wy, owx = 1.0f - wx;
    float w00 = owx * owy, w01 = owx * wy, w10 = wx * owy, w11 = wx * wy;

    float sx = 0.0f, sy = 0.0f, sz = 0.0f;
    unsigned offs[4] = {o00, o01, o10, o11};
    float    wr[4]   = {w00, w01, w10, w11};
#pragma unroll
    for (int r = 0; r < 4; r++) {
        unsigned o = offs[r];
        uint2 u = pXY[o];                                      // LDG.64
        unsigned uz = pZ[o];                                   // LDG.32
        __half2 a = *reinterpret_cast<__half2*>(&u.x);         // (x[o],   y[o])
        __half2 bq = *reinterpret_cast<__half2*>(&u.y);        // (x[o+1], y[o+1])
        __half2 cz = *reinterpret_cast<__half2*>(&uz);         // (z[o],   z[o+1])
        float2 f0 = __half22float2(a);
        float2 f1 = __half22float2(bq);
        float2 fz2 = __half22float2(cz);
        float w = wr[r];
        sx += w * (owz * f0.x + wz * f1.x);
        sy += w * (owz * f0.y + wz * f1.y);
        sz += w * (owz * fz2.x + wz * fz2.y);
    }

    float rx = dx + sx;
    float ry = dy + sy;
    float rz = dz + sz;

    if (AOS_OUT) {
        float* __restrict__ out = dstA + (size_t)idx * 3u;
        out[0] = rx;
        out[1] = ry;
        out[2] = rz;
    } else {
        store_all(idx, b, v, rx, ry, rz, dstF, dstXY, dstZ);
    }
}

extern "C" void kernel_launch(void* const* d_in, const int* in_sizes, int n_in,
                              void* d_out, int out_size)
{
    const float* vel = (const float*)d_in[0];
    float* out = (float*)d_out;
    float *fa, *fb; uint2 *xa, *xb; unsigned *za, *zb;
    cudaGetSymbolAddress((void**)&fa, g_f32a);
    cudaGetSymbolAddress((void**)&fb, g_f32b);
    cudaGetSymbolAddress((void**)&xa, g_pxa);
    cudaGetSymbolAddress((void**)&xb, g_pxb);
    cudaGetSymbolAddress((void**)&za, g_pza);
    cudaGetSymbolAddress((void**)&zb, g_pzb);

    const int threads = 256;
    const int blocksV = (NTOT + threads - 1) / threads;
    const float s0 = 1.0f / 128.0f;   // OUT_TIME_PT / 2^INT_STEPS

    // v0 = vel / 128 into fp32 SoA + pair arrays
    init_fields<<<blocksV, threads>>>(vel, fa, xa, za, s0);
    // 7 squaring steps; last writes float3 AoS directly into d_out
    vstep_p<0><<<blocksV, threads>>>(fa, xa, za, fb, xb, zb, nullptr);
    vstep_p<0><<<blocksV, threads>>>(fb, xb, zb, fa, xa, za, nullptr);
    vstep_p<0><<<blocksV, threads>>>(fa, xa, za, fb, xb, zb, nullptr);
    vstep_p<0><<<blocksV, threads>>>(fb, xb, zb, fa, xa, za, nullptr);
    vstep_p<0><<<blocksV, threads>>>(fa, xa, za, fb, xb, zb, nullptr);
    vstep_p<0><<<blocksV, threads>>>(fb, xb, zb, fa, xa, za, nullptr);
    vstep_p<1><<<blocksV, threads>>>(fa, xa, za, nullptr, nullptr, nullptr, out);
}